// round 13
// baseline (speedup 1.0000x reference)
#include <cuda_runtime.h>
#include <cuda_fp16.h>
#include <cstdint>

#define N_NODES 100000
#define N_EDGES 1600000
#define N_GRAPHS 256
#define D 128
#define L 3
#define PROJ 128
#define NUM_CLASSES 10

// ---------------- device scratch ----------------
__device__ float g_h[N_NODES * D];
__device__ float g_agg[N_NODES * D];
__device__ int   g_counts[N_NODES];
__device__ int   g_offs[N_NODES];
__device__ int   g_cursor[N_NODES];
__device__ int   g_bsum[128];
__device__ int   g_eidx[N_EDGES];
__device__ int   g_cg[N_GRAPHS];
__device__ float g_pooled[L * N_GRAPHS * D];
// packed mma-fragment fp16 weights: [l][mat(2)][2048] uint4; mat: 0=w1(BN-folded) 1=w2
__device__ __align__(16) uint4 g_wpack[L * 2 * 2048];
__device__ float g_b1e[L * D];
__device__ int   g_is64;

// ---------------- dtype detection: int64 vs int32 indices ----------------
__global__ void detect_kernel(const int* __restrict__ ei_words) {
    int all0 = 1;
    for (int i = 1; i < 128; i += 2)
        if (ei_words[i] != 0) { all0 = 0; break; }
    g_is64 = all0;
}

__device__ __forceinline__ int idx_at(const void* p, long long i) {
    if (g_is64) return (int)__ldg(&((const long long*)p)[i]);
    return __ldg(&((const int*)p)[i]);
}

// ---------------- setup kernels ----------------
__global__ void zero_kernel() {
    int i = blockIdx.x * blockDim.x + threadIdx.x;
    if (i < N_NODES) g_counts[i] = 0;
    if (i < N_GRAPHS) g_cg[i] = 0;
    if (i < L * N_GRAPHS * D) g_pooled[i] = 0.f;
}

__global__ void hist_edges(const void* __restrict__ ei) {
    int e = blockIdx.x * blockDim.x + threadIdx.x;
    if (e < N_EDGES) {
        int d = idx_at(ei, (long long)N_EDGES + e);
        atomicAdd(&g_counts[d], 1);
    }
}

// smem histogram: batch is sorted so each block touches few graphs
__global__ void hist_batch(const void* __restrict__ batch) {
    __shared__ int sh[N_GRAPHS];
    int tid = threadIdx.x;
    if (tid < N_GRAPHS) sh[tid] = 0;
    __syncthreads();
    int i = blockIdx.x * 1024 + tid;
    if (i < N_NODES) atomicAdd(&sh[idx_at(batch, i)], 1);
    __syncthreads();
    if (tid < N_GRAPHS && sh[tid]) atomicAdd(&g_cg[tid], sh[tid]);
}

__global__ void scan1() {
    __shared__ int s[1024];
    int i = blockIdx.x * 1024 + threadIdx.x;
    int v = (i < N_NODES) ? g_counts[i] : 0;
    s[threadIdx.x] = v;
    __syncthreads();
    for (int d = 1; d < 1024; d <<= 1) {
        int t = 0;
        if ((int)threadIdx.x >= d) t = s[threadIdx.x - d];
        __syncthreads();
        s[threadIdx.x] += t;
        __syncthreads();
    }
    if (i < N_NODES) g_offs[i] = s[threadIdx.x] - v;  // exclusive
    if (threadIdx.x == 1023) g_bsum[blockIdx.x] = s[1023];
}

// parallel exclusive scan of 98 block sums (1 block, 128 threads)
__global__ void scan2() {
    __shared__ int s[128];
    int t = threadIdx.x;
    int v = (t < 98) ? g_bsum[t] : 0;
    s[t] = v;
    __syncthreads();
    for (int d = 1; d < 128; d <<= 1) {
        int tmp = 0;
        if (t >= d) tmp = s[t - d];
        __syncthreads();
        s[t] += tmp;
        __syncthreads();
    }
    if (t < 98) g_bsum[t] = s[t] - v;  // exclusive
}

__global__ void scan3() {
    int i = blockIdx.x * blockDim.x + threadIdx.x;
    if (i < N_NODES) {
        int off = g_offs[i] + g_bsum[i >> 10];
        g_offs[i] = off;
        g_cursor[i] = off;
    }
}

__global__ void scatter_edges(const void* __restrict__ ei) {
    int e = blockIdx.x * blockDim.x + threadIdx.x;
    if (e < N_EDGES) {
        int d = idx_at(ei, (long long)N_EDGES + e);
        int s = idx_at(ei, e);
        int p = atomicAdd(&g_cursor[d], 1);
        g_eidx[p] = s;
    }
}

// ---------------- weight conversion: fold BN, fp16, pack to fragment order ----------------
__device__ __forceinline__ uint32_t pack2h(float a, float b) {
    __half ha = __float2half(a), hb = __float2half(b);
    return (uint32_t)(*(unsigned short*)&ha) | ((uint32_t)(*(unsigned short*)&hb) << 16);
}

__global__ void convert_weights(const float* __restrict__ W1, const float* __restrict__ W2,
                                const float* __restrict__ b1,
                                const float* __restrict__ bng, const float* __restrict__ bnb,
                                const float* __restrict__ bnm, const float* __restrict__ bnv) {
    int t = blockIdx.x * blockDim.x + threadIdx.x;
    if (t < L * D) {
        float scale = bng[t] * rsqrtf(bnv[t] + 1e-5f);
        g_b1e[t] = (b1[t] - bnm[t]) * scale + bnb[t];
    }
    if (t >= L * 2 * 2048) return;
    int l = t / (2 * 2048);
    int r = t % (2 * 2048);
    int mat = r / 2048;          // 0=w1 (BN-folded) 1=w2
    int fg = (r % 2048) / 32;    // kk*8+nbp
    int lane = r % 32;
    int kk = fg >> 3, nbp = fg & 7;
    int g = lane >> 2, t4 = lane & 3;
    int kb = kk * 16 + t4 * 2;
    int n0 = (2 * nbp) * 8 + g;
    int n1 = n0 + 8;
    const float* W = (mat == 0) ? W1 : W2;
    float s0 = 1.f, s1 = 1.f;
    if (mat == 0) {
        s0 = bng[l * D + n0] * rsqrtf(bnv[l * D + n0] + 1e-5f);
        s1 = bng[l * D + n1] * rsqrtf(bnv[l * D + n1] + 1e-5f);
    }
    const float* Wl = W + l * D * D;
    uint4 v;
    v.x = pack2h(Wl[kb * D + n0] * s0, Wl[(kb + 1) * D + n0] * s0);
    v.y = pack2h(Wl[(kb + 8) * D + n0] * s0, Wl[(kb + 9) * D + n0] * s0);
    v.z = pack2h(Wl[kb * D + n1] * s1, Wl[(kb + 1) * D + n1] * s1);
    v.w = pack2h(Wl[(kb + 8) * D + n1] * s1, Wl[(kb + 9) * D + n1] * s1);
    g_wpack[t] = v;
}

// ---------------- aggregation: agg[i] = h[i] + sum_{j->i} h[j] ----------------
// high-occupancy, unroll-8 gather: 8 independent edge-row loads in flight per warp
__global__ void aggregate_kernel(const float* __restrict__ x, int l) {
    int wid = threadIdx.x >> 5, lane = threadIdx.x & 31;
    int node = blockIdx.x * 8 + wid;
    if (node >= N_NODES) return;
    const float4* h4 = (const float4*)((l == 0) ? x : (const float*)g_h);
    float4 a0 = h4[node * 32 + lane];
    float4 a1 = make_float4(0.f, 0.f, 0.f, 0.f);
    float4 a2 = make_float4(0.f, 0.f, 0.f, 0.f);
    float4 a3 = make_float4(0.f, 0.f, 0.f, 0.f);
    int s = g_offs[node];
    int e = s + g_counts[node];
    int i = s;
    for (; i + 8 <= e; i += 8) {
        int s0 = __ldg(&g_eidx[i]);
        int s1 = __ldg(&g_eidx[i + 1]);
        int s2 = __ldg(&g_eidx[i + 2]);
        int s3 = __ldg(&g_eidx[i + 3]);
        int s4 = __ldg(&g_eidx[i + 4]);
        int s5 = __ldg(&g_eidx[i + 5]);
        int s6 = __ldg(&g_eidx[i + 6]);
        int s7 = __ldg(&g_eidx[i + 7]);
        float4 v0 = __ldg(&h4[s0 * 32 + lane]);
        float4 v1 = __ldg(&h4[s1 * 32 + lane]);
        float4 v2 = __ldg(&h4[s2 * 32 + lane]);
        float4 v3 = __ldg(&h4[s3 * 32 + lane]);
        float4 v4 = __ldg(&h4[s4 * 32 + lane]);
        float4 v5 = __ldg(&h4[s5 * 32 + lane]);
        float4 v6 = __ldg(&h4[s6 * 32 + lane]);
        float4 v7 = __ldg(&h4[s7 * 32 + lane]);
        a0.x += v0.x + v4.x; a0.y += v0.y + v4.y; a0.z += v0.z + v4.z; a0.w += v0.w + v4.w;
        a1.x += v1.x + v5.x; a1.y += v1.y + v5.y; a1.z += v1.z + v5.z; a1.w += v1.w + v5.w;
        a2.x += v2.x + v6.x; a2.y += v2.y + v6.y; a2.z += v2.z + v6.z; a2.w += v2.w + v6.w;
        a3.x += v3.x + v7.x; a3.y += v3.y + v7.y; a3.z += v3.z + v7.z; a3.w += v3.w + v7.w;
    }
    for (; i + 4 <= e; i += 4) {
        int s0 = __ldg(&g_eidx[i]);
        int s1 = __ldg(&g_eidx[i + 1]);
        int s2 = __ldg(&g_eidx[i + 2]);
        int s3 = __ldg(&g_eidx[i + 3]);
        float4 v0 = __ldg(&h4[s0 * 32 + lane]);
        float4 v1 = __ldg(&h4[s1 * 32 + lane]);
        float4 v2 = __ldg(&h4[s2 * 32 + lane]);
        float4 v3 = __ldg(&h4[s3 * 32 + lane]);
        a0.x += v0.x; a0.y += v0.y; a0.z += v0.z; a0.w += v0.w;
        a1.x += v1.x; a1.y += v1.y; a1.z += v1.z; a1.w += v1.w;
        a2.x += v2.x; a2.y += v2.y; a2.z += v2.z; a2.w += v2.w;
        a3.x += v3.x; a3.y += v3.y; a3.z += v3.z; a3.w += v3.w;
    }
    for (; i < e; i++) {
        int src = __ldg(&g_eidx[i]);
        float4 v = __ldg(&h4[src * 32 + lane]);
        a0.x += v.x; a0.y += v.y; a0.z += v.z; a0.w += v.w;
    }
    a0.x += a1.x + a2.x + a3.x;
    a0.y += a1.y + a2.y + a3.y;
    a0.z += a1.z + a2.z + a3.z;
    a0.w += a1.w + a2.w + a3.w;
    ((float4*)g_agg)[node * 32 + lane] = a0;
}

// ---------------- MLP via fp16 2-term compensated mma ----------------
__device__ __forceinline__ void mma_f16(float* c,
                                        uint32_t a0, uint32_t a1, uint32_t a2, uint32_t a3,
                                        uint32_t b0, uint32_t b1) {
    asm volatile(
        "mma.sync.aligned.m16n8k16.row.col.f32.f16.f16.f32 "
        "{%0,%1,%2,%3}, {%4,%5,%6,%7}, {%8,%9}, {%0,%1,%2,%3};"
        : "+f"(c[0]), "+f"(c[1]), "+f"(c[2]), "+f"(c[3])
        : "r"(a0), "r"(a1), "r"(a2), "r"(a3), "r"(b0), "r"(b1));
}

#define SM_PITCH 136

__device__ __forceinline__ void gemm_pass(const __half* sA, const uint4* __restrict__ wp,
                                          int r0, int lane, int t4, float acc[16][4]) {
#pragma unroll
    for (int kk = 0; kk < 8; kk++) {
        int kb = kk * 16 + t4 * 2;
        uint32_t a0 = *(const uint32_t*)(sA + r0 * SM_PITCH + kb);
        uint32_t a1 = *(const uint32_t*)(sA + (r0 + 8) * SM_PITCH + kb);
        uint32_t a2 = *(const uint32_t*)(sA + r0 * SM_PITCH + kb + 8);
        uint32_t a3 = *(const uint32_t*)(sA + (r0 + 8) * SM_PITCH + kb + 8);
        const uint4* base = wp + kk * 8 * 32 + lane;
#pragma unroll
        for (int nbp = 0; nbp < 8; nbp++) {
            uint4 b = __ldg(base + nbp * 32);
            mma_f16(acc[2 * nbp], a0, a1, a2, a3, b.x, b.y);
            mma_f16(acc[2 * nbp + 1], a0, a1, a2, a3, b.z, b.w);
        }
    }
}

// split fp32 -> fp16 hi + fp16 lo (hi+lo covers ~22 mantissa bits)
__device__ __forceinline__ void store_split(__half* sHi, __half* sLo,
                                            int r, int c, float x, float y) {
    __half hx = __float2half(x), hy = __float2half(y);
    unsigned int uh = (unsigned)(*(unsigned short*)&hx) | ((unsigned)(*(unsigned short*)&hy) << 16);
    __half lx = __float2half(x - __half2float(hx));
    __half ly = __float2half(y - __half2float(hy));
    unsigned int ul = (unsigned)(*(unsigned short*)&lx) | ((unsigned)(*(unsigned short*)&ly) << 16);
    *(unsigned int*)(sHi + r * SM_PITCH + c) = uh;
    *(unsigned int*)(sLo + r * SM_PITCH + c) = ul;
}

#define SMEM_MLP (2 * 128 * SM_PITCH * 2)

__global__ void __launch_bounds__(256) mlp_kernel(int l, const float* __restrict__ b2all) {
    extern __shared__ __half sm[];
    __half* sHi = sm;
    __half* sLo = sm + 128 * SM_PITCH;
    const int tid = threadIdx.x;
    const int tile = blockIdx.x * 128;

    // load agg tile (coalesced), split to hi/lo fp16
    for (int i = tid; i < 128 * 128 / 2; i += 256) {
        int r = i >> 6;           // 0..127
        int c = (i & 63) * 2;     // even columns
        int row = tile + r;
        float2 v = (row < N_NODES) ? *(const float2*)&g_agg[row * 128 + c]
                                   : make_float2(0.f, 0.f);
        store_split(sHi, sLo, r, c, v.x, v.y);
    }
    __syncthreads();

    const int wid = tid >> 5, lane = tid & 31;
    const int g = lane >> 2, t4 = lane & 3;
    const int r0 = wid * 16 + g;

    const uint4* wl = g_wpack + l * 2 * 2048;
    const float* b1e = g_b1e + l * D;
    const float* b2 = b2all + l * D;

    float acc[16][4];
#pragma unroll
    for (int nb = 0; nb < 16; nb++)
#pragma unroll
        for (int j = 0; j < 4; j++) acc[nb][j] = 0.f;

    // GEMM1: 2-term fp16 (A_hi + A_lo) * W1, BN folded into W1/b1e
    gemm_pass(sHi, wl + 0 * 2048, r0, lane, t4, acc);
    gemm_pass(sLo, wl + 0 * 2048, r0, lane, t4, acc);
    __syncthreads();

    // epilogue1: +b1e, relu, resplit to smem
#pragma unroll
    for (int nb = 0; nb < 16; nb++) {
        int c0 = nb * 8 + t4 * 2;
        float bb0 = __ldg(&b1e[c0]), bb1 = __ldg(&b1e[c0 + 1]);
        float v00 = fmaxf(acc[nb][0] + bb0, 0.f);
        float v01 = fmaxf(acc[nb][1] + bb1, 0.f);
        float v10 = fmaxf(acc[nb][2] + bb0, 0.f);
        float v11 = fmaxf(acc[nb][3] + bb1, 0.f);
        store_split(sHi, sLo, r0, c0, v00, v01);
        store_split(sHi, sLo, r0 + 8, c0, v10, v11);
    }
    __syncthreads();

#pragma unroll
    for (int nb = 0; nb < 16; nb++)
#pragma unroll
        for (int j = 0; j < 4; j++) acc[nb][j] = 0.f;

    // GEMM2: 2-term fp16
    gemm_pass(sHi, wl + 1 * 2048, r0, lane, t4, acc);
    gemm_pass(sLo, wl + 1 * 2048, r0, lane, t4, acc);

    // epilogue2: +b2, relu, store h
    int row0 = tile + r0;
    int row1 = tile + r0 + 8;
#pragma unroll
    for (int nb = 0; nb < 16; nb++) {
        int c0 = nb * 8 + t4 * 2;
        float bb0 = __ldg(&b2[c0]), bb1 = __ldg(&b2[c0 + 1]);
        float v00 = fmaxf(acc[nb][0] + bb0, 0.f);
        float v01 = fmaxf(acc[nb][1] + bb1, 0.f);
        float v10 = fmaxf(acc[nb][2] + bb0, 0.f);
        float v11 = fmaxf(acc[nb][3] + bb1, 0.f);
        if (row0 < N_NODES) *(float2*)&g_h[row0 * 128 + c0] = make_float2(v00, v01);
        if (row1 < N_NODES) *(float2*)&g_h[row1 * 128 + c0] = make_float2(v10, v11);
    }
}

// ---------------- pooling: segment-sum of h into pooled[l] ----------------
#define POOL_NODES 128
__global__ void pool_kernel(const void* __restrict__ batch, int l) {
    int t = threadIdx.x;  // 0..127 feature index
    int start = blockIdx.x * POOL_NODES;
    if (start >= N_NODES) return;
    int end = min(start + POOL_NODES, N_NODES);
    int cur = idx_at(batch, start);
    float acc = 0.f;
    for (int n = start; n < end; n++) {
        int gid = idx_at(batch, n);
        if (gid != cur) {
            atomicAdd(&g_pooled[(l * N_GRAPHS + cur) * D + t], acc);
            acc = 0.f;
            cur = gid;
        }
        acc += g_h[n * D + t];
    }
    atomicAdd(&g_pooled[(l * N_GRAPHS + cur) * D + t], acc);
}

// ---------------- head ----------------
__global__ void head_kernel(const float* __restrict__ Wp, const float* __restrict__ bp,
                            const float* __restrict__ Wc, const float* __restrict__ bc,
                            float* __restrict__ out) {
    __shared__ float zs[PROJ];
    int gph = blockIdx.x, t = threadIdx.x;
    float inv = 1.f / fmaxf((float)g_cg[gph], 1.f);
    float acc = bp[t];
#pragma unroll
    for (int l = 0; l < L; l++) {
        const float* pl = &g_pooled[(l * N_GRAPHS + gph) * D];
#pragma unroll 4
        for (int k = 0; k < D; k++) acc += pl[k] * inv * Wp[(l * D + k) * PROJ + t];
    }
    zs[t] = acc;
    out[gph * PROJ + t] = acc;
    __syncthreads();
    if (t < NUM_CLASSES) {
        float la = bc[t];
        for (int k = 0; k < PROJ; k++) la += zs[k] * Wc[k * NUM_CLASSES + t];
        out[N_GRAPHS * PROJ + gph * NUM_CLASSES + t] = la;
    }
}

// ---------------- launch ----------------
extern "C" void kernel_launch(void* const* d_in, const int* in_sizes, int n_in,
                              void* d_out, int out_size) {
    const float* x = (const float*)d_in[0];
    const void* ei = d_in[1];
    const void* batch = d_in[2];
    const float* W1 = (const float*)d_in[3];
    const float* b1 = (const float*)d_in[4];
    const float* bng = (const float*)d_in[5];
    const float* bnb = (const float*)d_in[6];
    const float* bnm = (const float*)d_in[7];
    const float* bnv = (const float*)d_in[8];
    const float* W2 = (const float*)d_in[9];
    const float* b2 = (const float*)d_in[10];
    const float* Wp = (const float*)d_in[11];
    const float* bp = (const float*)d_in[12];
    const float* Wc = (const float*)d_in[13];
    const float* bc = (const float*)d_in[14];
    float* out = (float*)d_out;

    cudaFuncSetAttribute(mlp_kernel, cudaFuncAttributeMaxDynamicSharedMemorySize, SMEM_MLP);

    detect_kernel<<<1, 1>>>((const int*)ei);
    zero_kernel<<<400, 256>>>();
    hist_edges<<<(N_EDGES + 255) / 256, 256>>>(ei);
    hist_batch<<<98, 1024>>>(batch);
    scan1<<<98, 1024>>>();
    scan2<<<1, 128>>>();
    scan3<<<(N_NODES + 255) / 256, 256>>>();
    scatter_edges<<<(N_EDGES + 255) / 256, 256>>>(ei);
    convert_weights<<<(L * 2 * 2048 + 255) / 256, 256>>>(W1, W2, b1, bng, bnb, bnm, bnv);

    for (int l = 0; l < L; l++) {
        aggregate_kernel<<<12500, 256>>>(x, l);
        mlp_kernel<<<(N_NODES + 127) / 128, 256, SMEM_MLP>>>(l, b2);
        pool_kernel<<<(N_NODES + POOL_NODES - 1) / POOL_NODES, 128>>>(batch, l);
    }
    head_kernel<<<N_GRAPHS, PROJ>>>(Wp, bp, Wc, bc, out);
}

// round 14
// speedup vs baseline: 1.0431x; 1.0431x over previous
#include <cuda_runtime.h>
#include <cuda_fp16.h>
#include <cstdint>

#define N_NODES 100000
#define N_EDGES 1600000
#define N_GRAPHS 256
#define D 128
#define L 3
#define PROJ 128
#define NUM_CLASSES 10

// ---------------- device scratch ----------------
__device__ float g_h[N_NODES * D];
__device__ float g_agg[N_NODES * D];
__device__ int   g_counts[N_NODES];
__device__ int   g_offs[N_NODES];
__device__ int   g_cursor[N_NODES];
__device__ int   g_bsum[128];
__device__ int   g_eidx[N_EDGES];
__device__ int   g_cg[N_GRAPHS];
__device__ float g_pooled[L * N_GRAPHS * D];
// packed mma-fragment fp16 weights: [l][mat(2)][2048] uint4; mat: 0=w1(BN-folded) 1=w2
__device__ __align__(16) uint4 g_wpack[L * 2 * 2048];
__device__ float g_b1e[L * D];
__device__ int   g_is64;

// ---------------- dtype detection: int64 vs int32 indices ----------------
__global__ void detect_kernel(const int* __restrict__ ei_words) {
    int all0 = 1;
    for (int i = 1; i < 128; i += 2)
        if (ei_words[i] != 0) { all0 = 0; break; }
    g_is64 = all0;
}

__device__ __forceinline__ int idx_at(const void* p, long long i) {
    if (g_is64) return (int)__ldg(&((const long long*)p)[i]);
    return __ldg(&((const int*)p)[i]);
}

// ---------------- setup kernels ----------------
__global__ void zero_kernel() {
    int i = blockIdx.x * blockDim.x + threadIdx.x;
    if (i < N_NODES) g_counts[i] = 0;
    if (i < N_GRAPHS) g_cg[i] = 0;
    if (i < L * N_GRAPHS * D) g_pooled[i] = 0.f;
}

__global__ void hist_edges(const void* __restrict__ ei) {
    int e = blockIdx.x * blockDim.x + threadIdx.x;
    if (e < N_EDGES) {
        int d = idx_at(ei, (long long)N_EDGES + e);
        atomicAdd(&g_counts[d], 1);
    }
}

// smem histogram: batch is sorted so each block touches few graphs
__global__ void hist_batch(const void* __restrict__ batch) {
    __shared__ int sh[N_GRAPHS];
    int tid = threadIdx.x;
    if (tid < N_GRAPHS) sh[tid] = 0;
    __syncthreads();
    int i = blockIdx.x * 1024 + tid;
    if (i < N_NODES) atomicAdd(&sh[idx_at(batch, i)], 1);
    __syncthreads();
    if (tid < N_GRAPHS && sh[tid]) atomicAdd(&g_cg[tid], sh[tid]);
}

__global__ void scan1() {
    __shared__ int s[1024];
    int i = blockIdx.x * 1024 + threadIdx.x;
    int v = (i < N_NODES) ? g_counts[i] : 0;
    s[threadIdx.x] = v;
    __syncthreads();
    for (int d = 1; d < 1024; d <<= 1) {
        int t = 0;
        if ((int)threadIdx.x >= d) t = s[threadIdx.x - d];
        __syncthreads();
        s[threadIdx.x] += t;
        __syncthreads();
    }
    if (i < N_NODES) g_offs[i] = s[threadIdx.x] - v;  // exclusive
    if (threadIdx.x == 1023) g_bsum[blockIdx.x] = s[1023];
}

// parallel exclusive scan of 98 block sums (1 block, 128 threads)
__global__ void scan2() {
    __shared__ int s[128];
    int t = threadIdx.x;
    int v = (t < 98) ? g_bsum[t] : 0;
    s[t] = v;
    __syncthreads();
    for (int d = 1; d < 128; d <<= 1) {
        int tmp = 0;
        if (t >= d) tmp = s[t - d];
        __syncthreads();
        s[t] += tmp;
        __syncthreads();
    }
    if (t < 98) g_bsum[t] = s[t] - v;  // exclusive
}

__global__ void scan3() {
    int i = blockIdx.x * blockDim.x + threadIdx.x;
    if (i < N_NODES) {
        int off = g_offs[i] + g_bsum[i >> 10];
        g_offs[i] = off;
        g_cursor[i] = off;
    }
}

__global__ void scatter_edges(const void* __restrict__ ei) {
    int e = blockIdx.x * blockDim.x + threadIdx.x;
    if (e < N_EDGES) {
        int d = idx_at(ei, (long long)N_EDGES + e);
        int s = idx_at(ei, e);
        int p = atomicAdd(&g_cursor[d], 1);
        g_eidx[p] = s;
    }
}

// ---------------- weight conversion: fold BN, fp16, pack to fragment order ----------------
__device__ __forceinline__ uint32_t pack2h(float a, float b) {
    __half ha = __float2half(a), hb = __float2half(b);
    return (uint32_t)(*(unsigned short*)&ha) | ((uint32_t)(*(unsigned short*)&hb) << 16);
}

__global__ void convert_weights(const float* __restrict__ W1, const float* __restrict__ W2,
                                const float* __restrict__ b1,
                                const float* __restrict__ bng, const float* __restrict__ bnb,
                                const float* __restrict__ bnm, const float* __restrict__ bnv) {
    int t = blockIdx.x * blockDim.x + threadIdx.x;
    if (t < L * D) {
        float scale = bng[t] * rsqrtf(bnv[t] + 1e-5f);
        g_b1e[t] = (b1[t] - bnm[t]) * scale + bnb[t];
    }
    if (t >= L * 2 * 2048) return;
    int l = t / (2 * 2048);
    int r = t % (2 * 2048);
    int mat = r / 2048;          // 0=w1 (BN-folded) 1=w2
    int fg = (r % 2048) / 32;    // kk*8+nbp
    int lane = r % 32;
    int kk = fg >> 3, nbp = fg & 7;
    int g = lane >> 2, t4 = lane & 3;
    int kb = kk * 16 + t4 * 2;
    int n0 = (2 * nbp) * 8 + g;
    int n1 = n0 + 8;
    const float* W = (mat == 0) ? W1 : W2;
    float s0 = 1.f, s1 = 1.f;
    if (mat == 0) {
        s0 = bng[l * D + n0] * rsqrtf(bnv[l * D + n0] + 1e-5f);
        s1 = bng[l * D + n1] * rsqrtf(bnv[l * D + n1] + 1e-5f);
    }
    const float* Wl = W + l * D * D;
    uint4 v;
    v.x = pack2h(Wl[kb * D + n0] * s0, Wl[(kb + 1) * D + n0] * s0);
    v.y = pack2h(Wl[(kb + 8) * D + n0] * s0, Wl[(kb + 9) * D + n0] * s0);
    v.z = pack2h(Wl[kb * D + n1] * s1, Wl[(kb + 1) * D + n1] * s1);
    v.w = pack2h(Wl[(kb + 8) * D + n1] * s1, Wl[(kb + 9) * D + n1] * s1);
    g_wpack[t] = v;
}

// ---------------- aggregation: agg[i] = h[i] + sum_{j->i} h[j] ----------------
// high-occupancy, unroll-4 gather (proven optimum in R11/R12)
__global__ void aggregate_kernel(const float* __restrict__ x, int l) {
    int wid = threadIdx.x >> 5, lane = threadIdx.x & 31;
    int node = blockIdx.x * 8 + wid;
    if (node >= N_NODES) return;
    const float4* h4 = (const float4*)((l == 0) ? x : (const float*)g_h);
    float4 a0 = h4[node * 32 + lane];
    float4 a1 = make_float4(0.f, 0.f, 0.f, 0.f);
    float4 a2 = make_float4(0.f, 0.f, 0.f, 0.f);
    float4 a3 = make_float4(0.f, 0.f, 0.f, 0.f);
    int s = g_offs[node];
    int e = s + g_counts[node];
    int i = s;
    for (; i + 4 <= e; i += 4) {
        int s0 = __ldg(&g_eidx[i]);
        int s1 = __ldg(&g_eidx[i + 1]);
        int s2 = __ldg(&g_eidx[i + 2]);
        int s3 = __ldg(&g_eidx[i + 3]);
        float4 v0 = __ldg(&h4[s0 * 32 + lane]);
        float4 v1 = __ldg(&h4[s1 * 32 + lane]);
        float4 v2 = __ldg(&h4[s2 * 32 + lane]);
        float4 v3 = __ldg(&h4[s3 * 32 + lane]);
        a0.x += v0.x; a0.y += v0.y; a0.z += v0.z; a0.w += v0.w;
        a1.x += v1.x; a1.y += v1.y; a1.z += v1.z; a1.w += v1.w;
        a2.x += v2.x; a2.y += v2.y; a2.z += v2.z; a2.w += v2.w;
        a3.x += v3.x; a3.y += v3.y; a3.z += v3.z; a3.w += v3.w;
    }
    for (; i < e; i++) {
        int src = __ldg(&g_eidx[i]);
        float4 v = __ldg(&h4[src * 32 + lane]);
        a0.x += v.x; a0.y += v.y; a0.z += v.z; a0.w += v.w;
    }
    a0.x += a1.x + a2.x + a3.x;
    a0.y += a1.y + a2.y + a3.y;
    a0.z += a1.z + a2.z + a3.z;
    a0.w += a1.w + a2.w + a3.w;
    ((float4*)g_agg)[node * 32 + lane] = a0;
}

// ---------------- MLP via fp16 2-term compensated mma ----------------
__device__ __forceinline__ void mma_f16(float* c,
                                        uint32_t a0, uint32_t a1, uint32_t a2, uint32_t a3,
                                        uint32_t b0, uint32_t b1) {
    asm volatile(
        "mma.sync.aligned.m16n8k16.row.col.f32.f16.f16.f32 "
        "{%0,%1,%2,%3}, {%4,%5,%6,%7}, {%8,%9}, {%0,%1,%2,%3};"
        : "+f"(c[0]), "+f"(c[1]), "+f"(c[2]), "+f"(c[3])
        : "r"(a0), "r"(a1), "r"(a2), "r"(a3), "r"(b0), "r"(b1));
}

#define SM_PITCH 136

__device__ __forceinline__ void gemm_pass(const __half* sA, const uint4* __restrict__ wp,
                                          int r0, int lane, int t4, float acc[16][4]) {
#pragma unroll
    for (int kk = 0; kk < 8; kk++) {
        int kb = kk * 16 + t4 * 2;
        uint32_t a0 = *(const uint32_t*)(sA + r0 * SM_PITCH + kb);
        uint32_t a1 = *(const uint32_t*)(sA + (r0 + 8) * SM_PITCH + kb);
        uint32_t a2 = *(const uint32_t*)(sA + r0 * SM_PITCH + kb + 8);
        uint32_t a3 = *(const uint32_t*)(sA + (r0 + 8) * SM_PITCH + kb + 8);
        const uint4* base = wp + kk * 8 * 32 + lane;
#pragma unroll
        for (int nbp = 0; nbp < 8; nbp++) {
            uint4 b = __ldg(base + nbp * 32);
            mma_f16(acc[2 * nbp], a0, a1, a2, a3, b.x, b.y);
            mma_f16(acc[2 * nbp + 1], a0, a1, a2, a3, b.z, b.w);
        }
    }
}

// split fp32 -> fp16 hi + fp16 lo (hi+lo covers ~22 mantissa bits)
__device__ __forceinline__ void store_split(__half* sHi, __half* sLo,
                                            int r, int c, float x, float y) {
    __half hx = __float2half(x), hy = __float2half(y);
    unsigned int uh = (unsigned)(*(unsigned short*)&hx) | ((unsigned)(*(unsigned short*)&hy) << 16);
    __half lx = __float2half(x - __half2float(hx));
    __half ly = __float2half(y - __half2float(hy));
    unsigned int ul = (unsigned)(*(unsigned short*)&lx) | ((unsigned)(*(unsigned short*)&ly) << 16);
    *(unsigned int*)(sHi + r * SM_PITCH + c) = uh;
    *(unsigned int*)(sLo + r * SM_PITCH + c) = ul;
}

#define SMEM_MLP (2 * 128 * SM_PITCH * 2)

__global__ void __launch_bounds__(256) mlp_kernel(int l, const float* __restrict__ b2all) {
    extern __shared__ __half sm[];
    __half* sHi = sm;
    __half* sLo = sm + 128 * SM_PITCH;
    const int tid = threadIdx.x;
    const int tile = blockIdx.x * 128;

    // load agg tile (coalesced), split to hi/lo fp16
    for (int i = tid; i < 128 * 128 / 2; i += 256) {
        int r = i >> 6;           // 0..127
        int c = (i & 63) * 2;     // even columns
        int row = tile + r;
        float2 v = (row < N_NODES) ? *(const float2*)&g_agg[row * 128 + c]
                                   : make_float2(0.f, 0.f);
        store_split(sHi, sLo, r, c, v.x, v.y);
    }
    __syncthreads();

    const int wid = tid >> 5, lane = tid & 31;
    const int g = lane >> 2, t4 = lane & 3;
    const int r0 = wid * 16 + g;

    const uint4* wl = g_wpack + l * 2 * 2048;
    const float* b1e = g_b1e + l * D;
    const float* b2 = b2all + l * D;

    float acc[16][4];
#pragma unroll
    for (int nb = 0; nb < 16; nb++)
#pragma unroll
        for (int j = 0; j < 4; j++) acc[nb][j] = 0.f;

    // GEMM1: 2-term fp16 (A_hi + A_lo) * W1, BN folded into W1/b1e
    gemm_pass(sHi, wl + 0 * 2048, r0, lane, t4, acc);
    gemm_pass(sLo, wl + 0 * 2048, r0, lane, t4, acc);
    __syncthreads();

    // epilogue1: +b1e, relu, resplit to smem
#pragma unroll
    for (int nb = 0; nb < 16; nb++) {
        int c0 = nb * 8 + t4 * 2;
        float bb0 = __ldg(&b1e[c0]), bb1 = __ldg(&b1e[c0 + 1]);
        float v00 = fmaxf(acc[nb][0] + bb0, 0.f);
        float v01 = fmaxf(acc[nb][1] + bb1, 0.f);
        float v10 = fmaxf(acc[nb][2] + bb0, 0.f);
        float v11 = fmaxf(acc[nb][3] + bb1, 0.f);
        store_split(sHi, sLo, r0, c0, v00, v01);
        store_split(sHi, sLo, r0 + 8, c0, v10, v11);
    }
    __syncthreads();

#pragma unroll
    for (int nb = 0; nb < 16; nb++)
#pragma unroll
        for (int j = 0; j < 4; j++) acc[nb][j] = 0.f;

    // GEMM2: 2-term fp16
    gemm_pass(sHi, wl + 1 * 2048, r0, lane, t4, acc);
    gemm_pass(sLo, wl + 1 * 2048, r0, lane, t4, acc);

    // epilogue2: +b2, relu, store h
    int row0 = tile + r0;
    int row1 = tile + r0 + 8;
#pragma unroll
    for (int nb = 0; nb < 16; nb++) {
        int c0 = nb * 8 + t4 * 2;
        float bb0 = __ldg(&b2[c0]), bb1 = __ldg(&b2[c0 + 1]);
        float v00 = fmaxf(acc[nb][0] + bb0, 0.f);
        float v01 = fmaxf(acc[nb][1] + bb1, 0.f);
        float v10 = fmaxf(acc[nb][2] + bb0, 0.f);
        float v11 = fmaxf(acc[nb][3] + bb1, 0.f);
        if (row0 < N_NODES) *(float2*)&g_h[row0 * 128 + c0] = make_float2(v00, v01);
        if (row1 < N_NODES) *(float2*)&g_h[row1 * 128 + c0] = make_float2(v10, v11);
    }
}

// ---------------- pooling: segment-sum of h into pooled[l] ----------------
#define POOL_NODES 128
__global__ void pool_kernel(const void* __restrict__ batch, int l) {
    int t = threadIdx.x;  // 0..127 feature index
    int start = blockIdx.x * POOL_NODES;
    if (start >= N_NODES) return;
    int end = min(start + POOL_NODES, N_NODES);
    int cur = idx_at(batch, start);
    float acc = 0.f;
    for (int n = start; n < end; n++) {
        int gid = idx_at(batch, n);
        if (gid != cur) {
            atomicAdd(&g_pooled[(l * N_GRAPHS + cur) * D + t], acc);
            acc = 0.f;
            cur = gid;
        }
        acc += g_h[n * D + t];
    }
    atomicAdd(&g_pooled[(l * N_GRAPHS + cur) * D + t], acc);
}

// ---------------- head ----------------
__global__ void head_kernel(const float* __restrict__ Wp, const float* __restrict__ bp,
                            const float* __restrict__ Wc, const float* __restrict__ bc,
                            float* __restrict__ out) {
    __shared__ float zs[PROJ];
    int gph = blockIdx.x, t = threadIdx.x;
    float inv = 1.f / fmaxf((float)g_cg[gph], 1.f);
    float acc = bp[t];
#pragma unroll
    for (int l = 0; l < L; l++) {
        const float* pl = &g_pooled[(l * N_GRAPHS + gph) * D];
#pragma unroll 4
        for (int k = 0; k < D; k++) acc += pl[k] * inv * Wp[(l * D + k) * PROJ + t];
    }
    zs[t] = acc;
    out[gph * PROJ + t] = acc;
    __syncthreads();
    if (t < NUM_CLASSES) {
        float la = bc[t];
        for (int k = 0; k < PROJ; k++) la += zs[k] * Wc[k * NUM_CLASSES + t];
        out[N_GRAPHS * PROJ + gph * NUM_CLASSES + t] = la;
    }
}

// ---------------- launch ----------------
extern "C" void kernel_launch(void* const* d_in, const int* in_sizes, int n_in,
                              void* d_out, int out_size) {
    const float* x = (const float*)d_in[0];
    const void* ei = d_in[1];
    const void* batch = d_in[2];
    const float* W1 = (const float*)d_in[3];
    const float* b1 = (const float*)d_in[4];
    const float* bng = (const float*)d_in[5];
    const float* bnb = (const float*)d_in[6];
    const float* bnm = (const float*)d_in[7];
    const float* bnv = (const float*)d_in[8];
    const float* W2 = (const float*)d_in[9];
    const float* b2 = (const float*)d_in[10];
    const float* Wp = (const float*)d_in[11];
    const float* bp = (const float*)d_in[12];
    const float* Wc = (const float*)d_in[13];
    const float* bc = (const float*)d_in[14];
    float* out = (float*)d_out;

    cudaFuncSetAttribute(mlp_kernel, cudaFuncAttributeMaxDynamicSharedMemorySize, SMEM_MLP);

    detect_kernel<<<1, 1>>>((const int*)ei);
    zero_kernel<<<400, 256>>>();
    hist_edges<<<(N_EDGES + 255) / 256, 256>>>(ei);
    hist_batch<<<98, 1024>>>(batch);
    scan1<<<98, 1024>>>();
    scan2<<<1, 128>>>();
    scan3<<<(N_NODES + 255) / 256, 256>>>();
    scatter_edges<<<(N_EDGES + 255) / 256, 256>>>(ei);
    convert_weights<<<(L * 2 * 2048 + 255) / 256, 256>>>(W1, W2, b1, bng, bnb, bnm, bnv);

    for (int l = 0; l < L; l++) {
        aggregate_kernel<<<12500, 256>>>(x, l);
        mlp_kernel<<<(N_NODES + 127) / 128, 256, SMEM_MLP>>>(l, b2);
        pool_kernel<<<(N_NODES + POOL_NODES - 1) / POOL_NODES, 128>>>(batch, l);
    }
    head_kernel<<<N_GRAPHS, PROJ>>>(Wp, bp, Wc, bc, out);
}

// round 16
// speedup vs baseline: 1.2346x; 1.1836x over previous
#include <cuda_runtime.h>
#include <cuda_fp16.h>
#include <cstdint>

#define N_NODES 100000
#define N_EDGES 1600000
#define N_GRAPHS 256
#define D 128
#define L 3
#define PROJ 128
#define NUM_CLASSES 10

// ---------------- device scratch ----------------
__device__ float g_h[N_NODES * D];
__device__ float g_agg[N_NODES * D];
__device__ int   g_counts[N_NODES];
__device__ int   g_offs[N_NODES];
__device__ int   g_cursor[N_NODES];
__device__ int   g_bsum[128];
__device__ int   g_eidx[N_EDGES];
__device__ int   g_cg[N_GRAPHS];
__device__ float g_pooled[L * N_GRAPHS * D];
// packed mma-fragment fp16 weights: [l][mat(2)][2048] uint4; mat: 0=w1(BN-folded) 1=w2
__device__ __align__(16) uint4 g_wpack[L * 2 * 2048];
__device__ float g_b1e[L * D];
__device__ int   g_is64;

// ---------------- dtype detection: int64 vs int32 indices ----------------
__global__ void detect_kernel(const int* __restrict__ ei_words) {
    int all0 = 1;
    for (int i = 1; i < 128; i += 2)
        if (ei_words[i] != 0) { all0 = 0; break; }
    g_is64 = all0;
}

__device__ __forceinline__ int idx_at(const void* p, long long i) {
    if (g_is64) return (int)__ldg(&((const long long*)p)[i]);
    return __ldg(&((const int*)p)[i]);
}

// ---------------- setup kernels ----------------
__global__ void zero_kernel() {
    int i = blockIdx.x * blockDim.x + threadIdx.x;
    if (i < N_NODES) g_counts[i] = 0;
    if (i < N_GRAPHS) g_cg[i] = 0;
    if (i < L * N_GRAPHS * D) g_pooled[i] = 0.f;
}

__global__ void hist_edges(const void* __restrict__ ei) {
    int e = blockIdx.x * blockDim.x + threadIdx.x;
    if (e < N_EDGES) {
        int d = idx_at(ei, (long long)N_EDGES + e);
        atomicAdd(&g_counts[d], 1);
    }
}

// smem histogram: batch is sorted so each block touches few graphs
__global__ void hist_batch(const void* __restrict__ batch) {
    __shared__ int sh[N_GRAPHS];
    int tid = threadIdx.x;
    if (tid < N_GRAPHS) sh[tid] = 0;
    __syncthreads();
    int i = blockIdx.x * 1024 + tid;
    if (i < N_NODES) atomicAdd(&sh[idx_at(batch, i)], 1);
    __syncthreads();
    if (tid < N_GRAPHS && sh[tid]) atomicAdd(&g_cg[tid], sh[tid]);
}

__global__ void scan1() {
    __shared__ int s[1024];
    int i = blockIdx.x * 1024 + threadIdx.x;
    int v = (i < N_NODES) ? g_counts[i] : 0;
    s[threadIdx.x] = v;
    __syncthreads();
    for (int d = 1; d < 1024; d <<= 1) {
        int t = 0;
        if ((int)threadIdx.x >= d) t = s[threadIdx.x - d];
        __syncthreads();
        s[threadIdx.x] += t;
        __syncthreads();
    }
    if (i < N_NODES) g_offs[i] = s[threadIdx.x] - v;  // exclusive
    if (threadIdx.x == 1023) g_bsum[blockIdx.x] = s[1023];
}

// parallel exclusive scan of 98 block sums (1 block, 128 threads)
__global__ void scan2() {
    __shared__ int s[128];
    int t = threadIdx.x;
    int v = (t < 98) ? g_bsum[t] : 0;
    s[t] = v;
    __syncthreads();
    for (int d = 1; d < 128; d <<= 1) {
        int tmp = 0;
        if (t >= d) tmp = s[t - d];
        __syncthreads();
        s[t] += tmp;
        __syncthreads();
    }
    if (t < 98) g_bsum[t] = s[t] - v;  // exclusive
}

__global__ void scan3() {
    int i = blockIdx.x * blockDim.x + threadIdx.x;
    if (i < N_NODES) {
        int off = g_offs[i] + g_bsum[i >> 10];
        g_offs[i] = off;
        g_cursor[i] = off;
    }
}

__global__ void scatter_edges(const void* __restrict__ ei) {
    int e = blockIdx.x * blockDim.x + threadIdx.x;
    if (e < N_EDGES) {
        int d = idx_at(ei, (long long)N_EDGES + e);
        int s = idx_at(ei, e);
        int p = atomicAdd(&g_cursor[d], 1);
        g_eidx[p] = s;
    }
}

// ---------------- weight conversion: fold BN, fp16, pack to fragment order ----------------
__device__ __forceinline__ uint32_t pack2h(float a, float b) {
    __half ha = __float2half(a), hb = __float2half(b);
    return (uint32_t)(*(unsigned short*)&ha) | ((uint32_t)(*(unsigned short*)&hb) << 16);
}

__global__ void convert_weights(const float* __restrict__ W1, const float* __restrict__ W2,
                                const float* __restrict__ b1,
                                const float* __restrict__ bng, const float* __restrict__ bnb,
                                const float* __restrict__ bnm, const float* __restrict__ bnv) {
    int t = blockIdx.x * blockDim.x + threadIdx.x;
    if (t < L * D) {
        float scale = bng[t] * rsqrtf(bnv[t] + 1e-5f);
        g_b1e[t] = (b1[t] - bnm[t]) * scale + bnb[t];
    }
    if (t >= L * 2 * 2048) return;
    int l = t / (2 * 2048);
    int r = t % (2 * 2048);
    int mat = r / 2048;          // 0=w1 (BN-folded) 1=w2
    int fg = (r % 2048) / 32;    // kk*8+nbp
    int lane = r % 32;
    int kk = fg >> 3, nbp = fg & 7;
    int g = lane >> 2, t4 = lane & 3;
    int kb = kk * 16 + t4 * 2;
    int n0 = (2 * nbp) * 8 + g;
    int n1 = n0 + 8;
    const float* W = (mat == 0) ? W1 : W2;
    float s0 = 1.f, s1 = 1.f;
    if (mat == 0) {
        s0 = bng[l * D + n0] * rsqrtf(bnv[l * D + n0] + 1e-5f);
        s1 = bng[l * D + n1] * rsqrtf(bnv[l * D + n1] + 1e-5f);
    }
    const float* Wl = W + l * D * D;
    uint4 v;
    v.x = pack2h(Wl[kb * D + n0] * s0, Wl[(kb + 1) * D + n0] * s0);
    v.y = pack2h(Wl[(kb + 8) * D + n0] * s0, Wl[(kb + 9) * D + n0] * s0);
    v.z = pack2h(Wl[kb * D + n1] * s1, Wl[(kb + 1) * D + n1] * s1);
    v.w = pack2h(Wl[(kb + 8) * D + n1] * s1, Wl[(kb + 9) * D + n1] * s1);
    g_wpack[t] = v;
}

// ---------------- aggregation: agg[i] = h[i] + sum_{j->i} h[j] ----------------
// high-occupancy, unroll-4 gather (proven optimum in R11/R12)
__global__ void aggregate_kernel(const float* __restrict__ x, int l) {
    int wid = threadIdx.x >> 5, lane = threadIdx.x & 31;
    int node = blockIdx.x * 8 + wid;
    if (node >= N_NODES) return;
    const float4* h4 = (const float4*)((l == 0) ? x : (const float*)g_h);
    float4 a0 = h4[node * 32 + lane];
    float4 a1 = make_float4(0.f, 0.f, 0.f, 0.f);
    float4 a2 = make_float4(0.f, 0.f, 0.f, 0.f);
    float4 a3 = make_float4(0.f, 0.f, 0.f, 0.f);
    int s = g_offs[node];
    int e = s + g_counts[node];
    int i = s;
    for (; i + 4 <= e; i += 4) {
        int s0 = __ldg(&g_eidx[i]);
        int s1 = __ldg(&g_eidx[i + 1]);
        int s2 = __ldg(&g_eidx[i + 2]);
        int s3 = __ldg(&g_eidx[i + 3]);
        float4 v0 = __ldg(&h4[s0 * 32 + lane]);
        float4 v1 = __ldg(&h4[s1 * 32 + lane]);
        float4 v2 = __ldg(&h4[s2 * 32 + lane]);
        float4 v3 = __ldg(&h4[s3 * 32 + lane]);
        a0.x += v0.x; a0.y += v0.y; a0.z += v0.z; a0.w += v0.w;
        a1.x += v1.x; a1.y += v1.y; a1.z += v1.z; a1.w += v1.w;
        a2.x += v2.x; a2.y += v2.y; a2.z += v2.z; a2.w += v2.w;
        a3.x += v3.x; a3.y += v3.y; a3.z += v3.z; a3.w += v3.w;
    }
    for (; i < e; i++) {
        int src = __ldg(&g_eidx[i]);
        float4 v = __ldg(&h4[src * 32 + lane]);
        a0.x += v.x; a0.y += v.y; a0.z += v.z; a0.w += v.w;
    }
    a0.x += a1.x + a2.x + a3.x;
    a0.y += a1.y + a2.y + a3.y;
    a0.z += a1.z + a2.z + a3.z;
    a0.w += a1.w + a2.w + a3.w;
    ((float4*)g_agg)[node * 32 + lane] = a0;
}

// ---------------- MLP via fp16 2-term compensated mma, fused pooling ----------------
__device__ __forceinline__ void mma_f16(float* c,
                                        uint32_t a0, uint32_t a1, uint32_t a2, uint32_t a3,
                                        uint32_t b0, uint32_t b1) {
    asm volatile(
        "mma.sync.aligned.m16n8k16.row.col.f32.f16.f16.f32 "
        "{%0,%1,%2,%3}, {%4,%5,%6,%7}, {%8,%9}, {%0,%1,%2,%3};"
        : "+f"(c[0]), "+f"(c[1]), "+f"(c[2]), "+f"(c[3])
        : "r"(a0), "r"(a1), "r"(a2), "r"(a3), "r"(b0), "r"(b1));
}

#define SM_PITCH 136
#define SF_PITCH 132

__device__ __forceinline__ void gemm_pass(const __half* sA, const uint4* __restrict__ wp,
                                          int r0, int lane, int t4, float acc[16][4]) {
#pragma unroll
    for (int kk = 0; kk < 8; kk++) {
        int kb = kk * 16 + t4 * 2;
        uint32_t a0 = *(const uint32_t*)(sA + r0 * SM_PITCH + kb);
        uint32_t a1 = *(const uint32_t*)(sA + (r0 + 8) * SM_PITCH + kb);
        uint32_t a2 = *(const uint32_t*)(sA + r0 * SM_PITCH + kb + 8);
        uint32_t a3 = *(const uint32_t*)(sA + (r0 + 8) * SM_PITCH + kb + 8);
        const uint4* base = wp + kk * 8 * 32 + lane;
#pragma unroll
        for (int nbp = 0; nbp < 8; nbp++) {
            uint4 b = __ldg(base + nbp * 32);
            mma_f16(acc[2 * nbp], a0, a1, a2, a3, b.x, b.y);
            mma_f16(acc[2 * nbp + 1], a0, a1, a2, a3, b.z, b.w);
        }
    }
}

// split fp32 -> fp16 hi + fp16 lo (hi+lo covers ~22 mantissa bits)
__device__ __forceinline__ void store_split(__half* sHi, __half* sLo,
                                            int r, int c, float x, float y) {
    __half hx = __float2half(x), hy = __float2half(y);
    unsigned int uh = (unsigned)(*(unsigned short*)&hx) | ((unsigned)(*(unsigned short*)&hy) << 16);
    __half lx = __float2half(x - __half2float(hx));
    __half ly = __float2half(y - __half2float(hy));
    unsigned int ul = (unsigned)(*(unsigned short*)&lx) | ((unsigned)(*(unsigned short*)&ly) << 16);
    *(unsigned int*)(sHi + r * SM_PITCH + c) = uh;
    *(unsigned int*)(sLo + r * SM_PITCH + c) = ul;
}

// smem layout:
//   [0, SMEM_HALF)            : GEMM phase, two fp16 tiles (sHi, sLo); pool phase aliases
//                               this region as a 128 x SF_PITCH fp32 tile (sF, 67584 B)
//   [SMEM_HALF, SMEM_HALF+512): sB batch-gid array (NON-overlapping, persists all phases)
#define SMEM_HALF (2 * 128 * SM_PITCH * 2)   // 69632
#define SMEM_MLP  (SMEM_HALF + 512)          // 70144

__global__ void __launch_bounds__(256) mlp_kernel(int l, const void* __restrict__ batch,
                                                  const float* __restrict__ b2all) {
    extern __shared__ char smraw[];
    __half* sHi = (__half*)smraw;
    __half* sLo = sHi + 128 * SM_PITCH;
    float*  sF  = (float*)smraw;               // aliases sHi/sLo (used only after sync)
    int*    sB  = (int*)(smraw + SMEM_HALF);   // above both layouts, never clobbered
    const int tid = threadIdx.x;
    const int tile = blockIdx.x * 128;

    // batch gids for this tile (persist through all phases)
    if (tid < 128) {
        int row = tile + tid;
        sB[tid] = (row < N_NODES) ? idx_at(batch, row) : -1;
    }

    // load agg tile (coalesced), split to hi/lo fp16
    for (int i = tid; i < 128 * 128 / 2; i += 256) {
        int r = i >> 6;           // 0..127
        int c = (i & 63) * 2;     // even columns
        int row = tile + r;
        float2 v = (row < N_NODES) ? *(const float2*)&g_agg[row * 128 + c]
                                   : make_float2(0.f, 0.f);
        store_split(sHi, sLo, r, c, v.x, v.y);
    }
    __syncthreads();

    const int wid = tid >> 5, lane = tid & 31;
    const int g = lane >> 2, t4 = lane & 3;
    const int r0 = wid * 16 + g;

    const uint4* wl = g_wpack + l * 2 * 2048;
    const float* b1e = g_b1e + l * D;
    const float* b2 = b2all + l * D;

    float acc[16][4];
#pragma unroll
    for (int nb = 0; nb < 16; nb++)
#pragma unroll
        for (int j = 0; j < 4; j++) acc[nb][j] = 0.f;

    // GEMM1: 2-term fp16 (A_hi + A_lo) * W1, BN folded into W1/b1e
    gemm_pass(sHi, wl + 0 * 2048, r0, lane, t4, acc);
    gemm_pass(sLo, wl + 0 * 2048, r0, lane, t4, acc);
    __syncthreads();

    // epilogue1: +b1e, relu, resplit to smem
#pragma unroll
    for (int nb = 0; nb < 16; nb++) {
        int c0 = nb * 8 + t4 * 2;
        float bb0 = __ldg(&b1e[c0]), bb1 = __ldg(&b1e[c0 + 1]);
        float v00 = fmaxf(acc[nb][0] + bb0, 0.f);
        float v01 = fmaxf(acc[nb][1] + bb1, 0.f);
        float v10 = fmaxf(acc[nb][2] + bb0, 0.f);
        float v11 = fmaxf(acc[nb][3] + bb1, 0.f);
        store_split(sHi, sLo, r0, c0, v00, v01);
        store_split(sHi, sLo, r0 + 8, c0, v10, v11);
    }
    __syncthreads();

#pragma unroll
    for (int nb = 0; nb < 16; nb++)
#pragma unroll
        for (int j = 0; j < 4; j++) acc[nb][j] = 0.f;

    // GEMM2: 2-term fp16
    gemm_pass(sHi, wl + 1 * 2048, r0, lane, t4, acc);
    gemm_pass(sLo, wl + 1 * 2048, r0, lane, t4, acc);
    __syncthreads();  // all warps done reading sHi/sLo before sF overwrites them

    // epilogue2: +b2, relu -> g_h (skipped on last layer) and sF for fused pooling
    int row0 = tile + r0;
    int row1 = tile + r0 + 8;
    bool wr = (l < L - 1);
#pragma unroll
    for (int nb = 0; nb < 16; nb++) {
        int c0 = nb * 8 + t4 * 2;
        float bb0 = __ldg(&b2[c0]), bb1 = __ldg(&b2[c0 + 1]);
        float v00 = fmaxf(acc[nb][0] + bb0, 0.f);
        float v01 = fmaxf(acc[nb][1] + bb1, 0.f);
        float v10 = fmaxf(acc[nb][2] + bb0, 0.f);
        float v11 = fmaxf(acc[nb][3] + bb1, 0.f);
        *(float2*)&sF[r0 * SF_PITCH + c0] = make_float2(v00, v01);
        *(float2*)&sF[(r0 + 8) * SF_PITCH + c0] = make_float2(v10, v11);
        if (wr && row0 < N_NODES) *(float2*)&g_h[row0 * 128 + c0] = make_float2(v00, v01);
        if (wr && row1 < N_NODES) *(float2*)&g_h[row1 * 128 + c0] = make_float2(v10, v11);
    }
    __syncthreads();

    // fused pooling: run-length over the 128 (batch-sorted) rows in sF
    if (tid < 128) {
        int t = tid;
        int cur = sB[0];
        float pacc = 0.f;
#pragma unroll 4
        for (int r = 0; r < 128; r++) {
            int gid = sB[r];
            if (gid < 0) break;  // padding rows at the very end only
            if (gid != cur) {
                atomicAdd(&g_pooled[(l * N_GRAPHS + cur) * D + t], pacc);
                pacc = 0.f;
                cur = gid;
            }
            pacc += sF[r * SF_PITCH + t];
        }
        if (cur >= 0) atomicAdd(&g_pooled[(l * N_GRAPHS + cur) * D + t], pacc);
    }
}

// ---------------- head ----------------
__global__ void head_kernel(const float* __restrict__ Wp, const float* __restrict__ bp,
                            const float* __restrict__ Wc, const float* __restrict__ bc,
                            float* __restrict__ out) {
    __shared__ float zs[PROJ];
    int gph = blockIdx.x, t = threadIdx.x;
    float inv = 1.f / fmaxf((float)g_cg[gph], 1.f);
    float acc = bp[t];
#pragma unroll
    for (int l = 0; l < L; l++) {
        const float* pl = &g_pooled[(l * N_GRAPHS + gph) * D];
#pragma unroll 4
        for (int k = 0; k < D; k++) acc += pl[k] * inv * Wp[(l * D + k) * PROJ + t];
    }
    zs[t] = acc;
    out[gph * PROJ + t] = acc;
    __syncthreads();
    if (t < NUM_CLASSES) {
        float la = bc[t];
        for (int k = 0; k < PROJ; k++) la += zs[k] * Wc[k * NUM_CLASSES + t];
        out[N_GRAPHS * PROJ + gph * NUM_CLASSES + t] = la;
    }
}

// ---------------- launch ----------------
extern "C" void kernel_launch(void* const* d_in, const int* in_sizes, int n_in,
                              void* d_out, int out_size) {
    const float* x = (const float*)d_in[0];
    const void* ei = d_in[1];
    const void* batch = d_in[2];
    const float* W1 = (const float*)d_in[3];
    const float* b1 = (const float*)d_in[4];
    const float* bng = (const float*)d_in[5];
    const float* bnb = (const float*)d_in[6];
    const float* bnm = (const float*)d_in[7];
    const float* bnv = (const float*)d_in[8];
    const float* W2 = (const float*)d_in[9];
    const float* b2 = (const float*)d_in[10];
    const float* Wp = (const float*)d_in[11];
    const float* bp = (const float*)d_in[12];
    const float* Wc = (const float*)d_in[13];
    const float* bc = (const float*)d_in[14];
    float* out = (float*)d_out;

    cudaFuncSetAttribute(mlp_kernel, cudaFuncAttributeMaxDynamicSharedMemorySize, SMEM_MLP);

    detect_kernel<<<1, 1>>>((const int*)ei);
    zero_kernel<<<400, 256>>>();
    hist_edges<<<(N_EDGES + 255) / 256, 256>>>(ei);
    hist_batch<<<98, 1024>>>(batch);
    scan1<<<98, 1024>>>();
    scan2<<<1, 128>>>();
    scan3<<<(N_NODES + 255) / 256, 256>>>();
    scatter_edges<<<(N_EDGES + 255) / 256, 256>>>(ei);
    convert_weights<<<(L * 2 * 2048 + 255) / 256, 256>>>(W1, W2, b1, bng, bnb, bnm, bnv);

    for (int l = 0; l < L; l++) {
        aggregate_kernel<<<12500, 256>>>(x, l);
        mlp_kernel<<<(N_NODES + 127) / 128, 256, SMEM_MLP>>>(l, batch, b2);
    }
    head_kernel<<<N_GRAPHS, PROJ>>>(Wp, bp, Wc, bc, out);
}

// round 17
// speedup vs baseline: 1.7120x; 1.3866x over previous
#include <cuda_runtime.h>
#include <cuda_fp16.h>
#include <cstdint>

#define N_NODES 100000
#define N_EDGES 1600000
#define N_GRAPHS 256
#define D 128
#define L 3
#define PROJ 128
#define NUM_CLASSES 10

// ---------------- device scratch ----------------
__device__ float g_h[N_NODES * D];
__device__ float g_agg[N_NODES * D];
__device__ int   g_counts[N_NODES];
__device__ int   g_offs[N_NODES];
__device__ int   g_cursor[N_NODES];
__device__ int   g_bsum[128];
__device__ int   g_eidx[N_EDGES];
__device__ int   g_cg[N_GRAPHS];
__device__ float g_pooled[L * N_GRAPHS * D];
// packed mma-fragment fp16 weights: [l][mat(2)][2048] uint4; mat: 0=w1(BN-folded) 1=w2
__device__ __align__(16) uint4 g_wpack[L * 2 * 2048];
__device__ float g_b1e[L * D];
__device__ int   g_is64;

// ---------------- dtype detection: int64 vs int32 indices ----------------
__global__ void detect_kernel(const int* __restrict__ ei_words) {
    int all0 = 1;
    for (int i = 1; i < 128; i += 2)
        if (ei_words[i] != 0) { all0 = 0; break; }
    g_is64 = all0;
}

__device__ __forceinline__ int idx_at(const void* p, long long i) {
    if (g_is64) return (int)__ldg(&((const long long*)p)[i]);
    return __ldg(&((const int*)p)[i]);
}

// ---------------- setup kernels ----------------
__global__ void zero_kernel() {
    int i = blockIdx.x * blockDim.x + threadIdx.x;
    if (i < N_NODES) g_counts[i] = 0;
    if (i < N_GRAPHS) g_cg[i] = 0;
    if (i < L * N_GRAPHS * D) g_pooled[i] = 0.f;
}

__global__ void hist_edges(const void* __restrict__ ei) {
    int e = blockIdx.x * blockDim.x + threadIdx.x;
    if (e < N_EDGES) {
        int d = idx_at(ei, (long long)N_EDGES + e);
        atomicAdd(&g_counts[d], 1);
    }
}

// smem histogram: batch is sorted so each block touches few graphs
__global__ void hist_batch(const void* __restrict__ batch) {
    __shared__ int sh[N_GRAPHS];
    int tid = threadIdx.x;
    if (tid < N_GRAPHS) sh[tid] = 0;
    __syncthreads();
    int i = blockIdx.x * 1024 + tid;
    if (i < N_NODES) atomicAdd(&sh[idx_at(batch, i)], 1);
    __syncthreads();
    if (tid < N_GRAPHS && sh[tid]) atomicAdd(&g_cg[tid], sh[tid]);
}

__global__ void scan1() {
    __shared__ int s[1024];
    int i = blockIdx.x * 1024 + threadIdx.x;
    int v = (i < N_NODES) ? g_counts[i] : 0;
    s[threadIdx.x] = v;
    __syncthreads();
    for (int d = 1; d < 1024; d <<= 1) {
        int t = 0;
        if ((int)threadIdx.x >= d) t = s[threadIdx.x - d];
        __syncthreads();
        s[threadIdx.x] += t;
        __syncthreads();
    }
    if (i < N_NODES) g_offs[i] = s[threadIdx.x] - v;  // exclusive
    if (threadIdx.x == 1023) g_bsum[blockIdx.x] = s[1023];
}

// parallel exclusive scan of 98 block sums (1 block, 128 threads)
__global__ void scan2() {
    __shared__ int s[128];
    int t = threadIdx.x;
    int v = (t < 98) ? g_bsum[t] : 0;
    s[t] = v;
    __syncthreads();
    for (int d = 1; d < 128; d <<= 1) {
        int tmp = 0;
        if (t >= d) tmp = s[t - d];
        __syncthreads();
        s[t] += tmp;
        __syncthreads();
    }
    if (t < 98) g_bsum[t] = s[t] - v;  // exclusive
}

__global__ void scan3() {
    int i = blockIdx.x * blockDim.x + threadIdx.x;
    if (i < N_NODES) {
        int off = g_offs[i] + g_bsum[i >> 10];
        g_offs[i] = off;
        g_cursor[i] = off;
    }
}

__global__ void scatter_edges(const void* __restrict__ ei) {
    int e = blockIdx.x * blockDim.x + threadIdx.x;
    if (e < N_EDGES) {
        int d = idx_at(ei, (long long)N_EDGES + e);
        int s = idx_at(ei, e);
        int p = atomicAdd(&g_cursor[d], 1);
        g_eidx[p] = s;
    }
}

// ---------------- weight conversion: fold BN, fp16, pack to fragment order ----------------
__device__ __forceinline__ uint32_t pack2h(float a, float b) {
    __half ha = __float2half(a), hb = __float2half(b);
    return (uint32_t)(*(unsigned short*)&ha) | ((uint32_t)(*(unsigned short*)&hb) << 16);
}

__global__ void convert_weights(const float* __restrict__ W1, const float* __restrict__ W2,
                                const float* __restrict__ b1,
                                const float* __restrict__ bng, const float* __restrict__ bnb,
                                const float* __restrict__ bnm, const float* __restrict__ bnv) {
    int t = blockIdx.x * blockDim.x + threadIdx.x;
    if (t < L * D) {
        float scale = bng[t] * rsqrtf(bnv[t] + 1e-5f);
        g_b1e[t] = (b1[t] - bnm[t]) * scale + bnb[t];
    }
    if (t >= L * 2 * 2048) return;
    int l = t / (2 * 2048);
    int r = t % (2 * 2048);
    int mat = r / 2048;          // 0=w1 (BN-folded) 1=w2
    int fg = (r % 2048) / 32;    // kk*8+nbp
    int lane = r % 32;
    int kk = fg >> 3, nbp = fg & 7;
    int g = lane >> 2, t4 = lane & 3;
    int kb = kk * 16 + t4 * 2;
    int n0 = (2 * nbp) * 8 + g;
    int n1 = n0 + 8;
    const float* W = (mat == 0) ? W1 : W2;
    float s0 = 1.f, s1 = 1.f;
    if (mat == 0) {
        s0 = bng[l * D + n0] * rsqrtf(bnv[l * D + n0] + 1e-5f);
        s1 = bng[l * D + n1] * rsqrtf(bnv[l * D + n1] + 1e-5f);
    }
    const float* Wl = W + l * D * D;
    uint4 v;
    v.x = pack2h(Wl[kb * D + n0] * s0, Wl[(kb + 1) * D + n0] * s0);
    v.y = pack2h(Wl[(kb + 8) * D + n0] * s0, Wl[(kb + 9) * D + n0] * s0);
    v.z = pack2h(Wl[kb * D + n1] * s1, Wl[(kb + 1) * D + n1] * s1);
    v.w = pack2h(Wl[(kb + 8) * D + n1] * s1, Wl[(kb + 9) * D + n1] * s1);
    g_wpack[t] = v;
}

// ---------------- aggregation: agg[i] = h[i] + sum_{j->i} h[j] ----------------
// high-occupancy, unroll-4 gather (proven optimum in R11/R12)
__global__ void aggregate_kernel(const float* __restrict__ x, int l) {
    int wid = threadIdx.x >> 5, lane = threadIdx.x & 31;
    int node = blockIdx.x * 8 + wid;
    if (node >= N_NODES) return;
    const float4* h4 = (const float4*)((l == 0) ? x : (const float*)g_h);
    float4 a0 = h4[node * 32 + lane];
    float4 a1 = make_float4(0.f, 0.f, 0.f, 0.f);
    float4 a2 = make_float4(0.f, 0.f, 0.f, 0.f);
    float4 a3 = make_float4(0.f, 0.f, 0.f, 0.f);
    int s = g_offs[node];
    int e = s + g_counts[node];
    int i = s;
    for (; i + 4 <= e; i += 4) {
        int s0 = __ldg(&g_eidx[i]);
        int s1 = __ldg(&g_eidx[i + 1]);
        int s2 = __ldg(&g_eidx[i + 2]);
        int s3 = __ldg(&g_eidx[i + 3]);
        float4 v0 = __ldg(&h4[s0 * 32 + lane]);
        float4 v1 = __ldg(&h4[s1 * 32 + lane]);
        float4 v2 = __ldg(&h4[s2 * 32 + lane]);
        float4 v3 = __ldg(&h4[s3 * 32 + lane]);
        a0.x += v0.x; a0.y += v0.y; a0.z += v0.z; a0.w += v0.w;
        a1.x += v1.x; a1.y += v1.y; a1.z += v1.z; a1.w += v1.w;
        a2.x += v2.x; a2.y += v2.y; a2.z += v2.z; a2.w += v2.w;
        a3.x += v3.x; a3.y += v3.y; a3.z += v3.z; a3.w += v3.w;
    }
    for (; i < e; i++) {
        int src = __ldg(&g_eidx[i]);
        float4 v = __ldg(&h4[src * 32 + lane]);
        a0.x += v.x; a0.y += v.y; a0.z += v.z; a0.w += v.w;
    }
    a0.x += a1.x + a2.x + a3.x;
    a0.y += a1.y + a2.y + a3.y;
    a0.z += a1.z + a2.z + a3.z;
    a0.w += a1.w + a2.w + a3.w;
    ((float4*)g_agg)[node * 32 + lane] = a0;
}

// ---------------- MLP via single-pass fp16 mma, fused pooling ----------------
__device__ __forceinline__ void mma_f16(float* c,
                                        uint32_t a0, uint32_t a1, uint32_t a2, uint32_t a3,
                                        uint32_t b0, uint32_t b1) {
    asm volatile(
        "mma.sync.aligned.m16n8k16.row.col.f32.f16.f16.f32 "
        "{%0,%1,%2,%3}, {%4,%5,%6,%7}, {%8,%9}, {%0,%1,%2,%3};"
        : "+f"(c[0]), "+f"(c[1]), "+f"(c[2]), "+f"(c[3])
        : "r"(a0), "r"(a1), "r"(a2), "r"(a3), "r"(b0), "r"(b1));
}

#define SM_PITCH 136
#define SF_PITCH 128

__device__ __forceinline__ void gemm_pass(const __half* sA, const uint4* __restrict__ wp,
                                          int r0, int lane, int t4, float acc[16][4]) {
#pragma unroll
    for (int kk = 0; kk < 8; kk++) {
        int kb = kk * 16 + t4 * 2;
        uint32_t a0 = *(const uint32_t*)(sA + r0 * SM_PITCH + kb);
        uint32_t a1 = *(const uint32_t*)(sA + (r0 + 8) * SM_PITCH + kb);
        uint32_t a2 = *(const uint32_t*)(sA + r0 * SM_PITCH + kb + 8);
        uint32_t a3 = *(const uint32_t*)(sA + (r0 + 8) * SM_PITCH + kb + 8);
        const uint4* base = wp + kk * 8 * 32 + lane;
#pragma unroll
        for (int nbp = 0; nbp < 8; nbp++) {
            uint4 b = __ldg(base + nbp * 32);
            mma_f16(acc[2 * nbp], a0, a1, a2, a3, b.x, b.y);
            mma_f16(acc[2 * nbp + 1], a0, a1, a2, a3, b.z, b.w);
        }
    }
}

__device__ __forceinline__ void store_h2(__half* sH, int r, int c, float x, float y) {
    *(unsigned int*)(sH + r * SM_PITCH + c) = pack2h(x, y);
}

// smem layout:
//   GEMM phase : one fp16 tile sH [128 x SM_PITCH]        = 34816 B at offset 0
//   pool phase : fp32 tile sF [128 x SF_PITCH] (aliases)  = 65536 B at offset 0
//   sB batch-gid array (non-overlapping, persists)        = 512 B at offset 65536
#define SMEM_MLP (128 * SF_PITCH * 4 + 512)   // 66048

__global__ void __launch_bounds__(256) mlp_kernel(int l, const void* __restrict__ batch,
                                                  const float* __restrict__ b2all) {
    extern __shared__ char smraw[];
    __half* sH = (__half*)smraw;
    float*  sF = (float*)smraw;                        // aliases sH (used only after sync)
    int*    sB = (int*)(smraw + 128 * SF_PITCH * 4);   // above both layouts
    const int tid = threadIdx.x;
    const int tile = blockIdx.x * 128;

    // batch gids for this tile (persist through all phases)
    if (tid < 128) {
        int row = tile + tid;
        sB[tid] = (row < N_NODES) ? idx_at(batch, row) : -1;
    }

    // load agg tile (coalesced), convert to fp16
    for (int i = tid; i < 128 * 128 / 2; i += 256) {
        int r = i >> 6;           // 0..127
        int c = (i & 63) * 2;     // even columns
        int row = tile + r;
        float2 v = (row < N_NODES) ? *(const float2*)&g_agg[row * 128 + c]
                                   : make_float2(0.f, 0.f);
        store_h2(sH, r, c, v.x, v.y);
    }
    __syncthreads();

    const int wid = tid >> 5, lane = tid & 31;
    const int g = lane >> 2, t4 = lane & 3;
    const int r0 = wid * 16 + g;

    const uint4* wl = g_wpack + l * 2 * 2048;
    const float* b1e = g_b1e + l * D;
    const float* b2 = b2all + l * D;

    float acc[16][4];
#pragma unroll
    for (int nb = 0; nb < 16; nb++)
#pragma unroll
        for (int j = 0; j < 4; j++) acc[nb][j] = 0.f;

    // GEMM1: single-pass fp16 (BN folded into W1/b1e)
    gemm_pass(sH, wl + 0 * 2048, r0, lane, t4, acc);
    __syncthreads();

    // epilogue1: +b1e, relu, back to fp16 smem
#pragma unroll
    for (int nb = 0; nb < 16; nb++) {
        int c0 = nb * 8 + t4 * 2;
        float bb0 = __ldg(&b1e[c0]), bb1 = __ldg(&b1e[c0 + 1]);
        store_h2(sH, r0, c0, fmaxf(acc[nb][0] + bb0, 0.f), fmaxf(acc[nb][1] + bb1, 0.f));
        store_h2(sH, r0 + 8, c0, fmaxf(acc[nb][2] + bb0, 0.f), fmaxf(acc[nb][3] + bb1, 0.f));
    }
    __syncthreads();

#pragma unroll
    for (int nb = 0; nb < 16; nb++)
#pragma unroll
        for (int j = 0; j < 4; j++) acc[nb][j] = 0.f;

    // GEMM2: single-pass fp16
    gemm_pass(sH, wl + 1 * 2048, r0, lane, t4, acc);
    __syncthreads();  // all warps done reading sH before sF overwrites it

    // epilogue2: +b2, relu -> g_h (skipped on last layer) and sF for fused pooling
    int row0 = tile + r0;
    int row1 = tile + r0 + 8;
    bool wr = (l < L - 1);
#pragma unroll
    for (int nb = 0; nb < 16; nb++) {
        int c0 = nb * 8 + t4 * 2;
        float bb0 = __ldg(&b2[c0]), bb1 = __ldg(&b2[c0 + 1]);
        float v00 = fmaxf(acc[nb][0] + bb0, 0.f);
        float v01 = fmaxf(acc[nb][1] + bb1, 0.f);
        float v10 = fmaxf(acc[nb][2] + bb0, 0.f);
        float v11 = fmaxf(acc[nb][3] + bb1, 0.f);
        *(float2*)&sF[r0 * SF_PITCH + c0] = make_float2(v00, v01);
        *(float2*)&sF[(r0 + 8) * SF_PITCH + c0] = make_float2(v10, v11);
        if (wr && row0 < N_NODES) *(float2*)&g_h[row0 * 128 + c0] = make_float2(v00, v01);
        if (wr && row1 < N_NODES) *(float2*)&g_h[row1 * 128 + c0] = make_float2(v10, v11);
    }
    __syncthreads();

    // fused pooling: run-length over the 128 (batch-sorted) rows in sF
    if (tid < 128) {
        int t = tid;
        int cur = sB[0];
        float pacc = 0.f;
#pragma unroll 4
        for (int r = 0; r < 128; r++) {
            int gid = sB[r];
            if (gid < 0) break;  // padding rows at the very end only
            if (gid != cur) {
                atomicAdd(&g_pooled[(l * N_GRAPHS + cur) * D + t], pacc);
                pacc = 0.f;
                cur = gid;
            }
            pacc += sF[r * SF_PITCH + t];
        }
        if (cur >= 0) atomicAdd(&g_pooled[(l * N_GRAPHS + cur) * D + t], pacc);
    }
}

// ---------------- head ----------------
__global__ void head_kernel(const float* __restrict__ Wp, const float* __restrict__ bp,
                            const float* __restrict__ Wc, const float* __restrict__ bc,
                            float* __restrict__ out) {
    __shared__ float zs[PROJ];
    int gph = blockIdx.x, t = threadIdx.x;
    float inv = 1.f / fmaxf((float)g_cg[gph], 1.f);
    float acc = bp[t];
#pragma unroll
    for (int l = 0; l < L; l++) {
        const float* pl = &g_pooled[(l * N_GRAPHS + gph) * D];
#pragma unroll 4
        for (int k = 0; k < D; k++) acc += pl[k] * inv * Wp[(l * D + k) * PROJ + t];
    }
    zs[t] = acc;
    out[gph * PROJ + t] = acc;
    __syncthreads();
    if (t < NUM_CLASSES) {
        float la = bc[t];
        for (int k = 0; k < PROJ; k++) la += zs[k] * Wc[k * NUM_CLASSES + t];
        out[N_GRAPHS * PROJ + gph * NUM_CLASSES + t] = la;
    }
}

// ---------------- launch ----------------
extern "C" void kernel_launch(void* const* d_in, const int* in_sizes, int n_in,
                              void* d_out, int out_size) {
    const float* x = (const float*)d_in[0];
    const void* ei = d_in[1];
    const void* batch = d_in[2];
    const float* W1 = (const float*)d_in[3];
    const float* b1 = (const float*)d_in[4];
    const float* bng = (const float*)d_in[5];
    const float* bnb = (const float*)d_in[6];
    const float* bnm = (const float*)d_in[7];
    const float* bnv = (const float*)d_in[8];
    const float* W2 = (const float*)d_in[9];
    const float* b2 = (const float*)d_in[10];
    const float* Wp = (const float*)d_in[11];
    const float* bp = (const float*)d_in[12];
    const float* Wc = (const float*)d_in[13];
    const float* bc = (const float*)d_in[14];
    float* out = (float*)d_out;

    cudaFuncSetAttribute(mlp_kernel, cudaFuncAttributeMaxDynamicSharedMemorySize, SMEM_MLP);

    detect_kernel<<<1, 1>>>((const int*)ei);
    zero_kernel<<<400, 256>>>();
    hist_edges<<<(N_EDGES + 255) / 256, 256>>>(ei);
    hist_batch<<<98, 1024>>>(batch);
    scan1<<<98, 1024>>>();
    scan2<<<1, 128>>>();
    scan3<<<(N_NODES + 255) / 256, 256>>>();
    scatter_edges<<<(N_EDGES + 255) / 256, 256>>>(ei);
    convert_weights<<<(L * 2 * 2048 + 255) / 256, 256>>>(W1, W2, b1, bng, bnb, bnm, bnv);

    for (int l = 0; l < L; l++) {
        aggregate_kernel<<<12500, 256>>>(x, l);
        mlp_kernel<<<(N_NODES + 127) / 128, 256, SMEM_MLP>>>(l, batch, b2);
    }
    head_kernel<<<N_GRAPHS, PROJ>>>(Wp, bp, Wc, bc, out);
}